// round 1
// baseline (speedup 1.0000x reference)
#include <cuda_runtime.h>

#define B_ 4
#define N_ 8192
#define F_ 64

// Scratch (allocation-free rule: __device__ globals). 8 MB each.
__device__ float g_y[B_ * N_ * F_];
__device__ float g_z[B_ * N_ * F_];

// ---------------- packed f32x2 helpers (FFMA2 path) ----------------
__device__ __forceinline__ unsigned long long pk2(float x, float y) {
    unsigned long long r;
    asm("mov.b64 %0, {%1, %2};" : "=l"(r) : "f"(x), "f"(y));
    return r;
}
__device__ __forceinline__ unsigned long long fma2(unsigned long long a,
                                                   unsigned long long b,
                                                   unsigned long long c) {
    unsigned long long d;
    asm("fma.rn.f32x2 %0, %1, %2, %3;" : "=l"(d) : "l"(a), "l"(b), "l"(c));
    return d;
}
__device__ __forceinline__ float2 upk2(unsigned long long v) {
    float lo, hi;
    asm("mov.b64 {%0, %1}, %2;" : "=f"(lo), "=f"(hi) : "l"(v));
    return make_float2(lo, hi);
}

// ---------------- small GEMM: Y[r][g] = sum_f Z[r][f] * W[f][g] ----------------
// rows r over B*N = 32768. One CTA = 64 rows, 256 threads, W staged in smem.
__global__ __launch_bounds__(256) void zw_kernel(const float* __restrict__ Z,
                                                 const float* __restrict__ Wp,
                                                 float* __restrict__ Y) {
    __shared__ float Ws[64 * 65];
    __shared__ float Zs[64 * 65];
    const int tid = threadIdx.x;
    const int r0 = blockIdx.x * 64;

    #pragma unroll
    for (int i = tid; i < 4096; i += 256) {
        Ws[(i >> 6) * 65 + (i & 63)] = Wp[i];
    }
    const float4* Zv = reinterpret_cast<const float4*>(Z + (size_t)r0 * 64);
    #pragma unroll
    for (int i = tid; i < 1024; i += 256) {
        float4 v = Zv[i];
        int r = i >> 4, c = (i & 15) << 2;
        float* p = &Zs[r * 65 + c];
        p[0] = v.x; p[1] = v.y; p[2] = v.z; p[3] = v.w;
    }
    __syncthreads();

    const int r = tid >> 2;          // 0..63
    const int g0 = (tid & 3) << 4;   // 0,16,32,48
    float acc[16];
    #pragma unroll
    for (int j = 0; j < 16; j++) acc[j] = 0.f;

    #pragma unroll 8
    for (int f = 0; f < 64; f++) {
        float zv = Zs[r * 65 + f];
        #pragma unroll
        for (int j = 0; j < 16; j++)
            acc[j] = fmaf(zv, Ws[f * 65 + g0 + j], acc[j]);
    }

    float4* dst = reinterpret_cast<float4*>(Y + (size_t)(r0 + r) * 64 + g0);
    dst[0] = make_float4(acc[0], acc[1], acc[2], acc[3]);
    dst[1] = make_float4(acc[4], acc[5], acc[6], acc[7]);
    dst[2] = make_float4(acc[8], acc[9], acc[10], acc[11]);
    dst[3] = make_float4(acc[12], acc[13], acc[14], acc[15]);
}

// ---------------- big GEMM: O[b] = relu(A @ Y[b]) ----------------
// A: [N_, N_] row-major.  Y, O: per batch [N_, 64] row-major.
// BM=128, BN=64, BK=32, 128 threads, 8x8 thread tile, FFMA2 accumulators.
// A tile stored transposed in smem with XOR swizzle -> conflict-free STS & LDS.128.
__global__ __launch_bounds__(128) void gemm_relu_kernel(const float* __restrict__ A,
                                                        const float* __restrict__ Yall,
                                                        float* __restrict__ Oall) {
    __shared__ float As[32 * 128];  // [k][m] swizzled
    __shared__ float Bs[32 * 64];   // [k][g] row-major

    const int tid = threadIdx.x;
    const int tx = tid & 7;   // N dir: 8 * 8 = 64
    const int ty = tid >> 3;  // M dir: 16 * 8 = 128
    const int batch = blockIdx.x;
    const int m0 = blockIdx.y << 7;

    const float* __restrict__ Yb = Yall + (size_t)batch * (N_ * F_);
    float* __restrict__ Ob = Oall + (size_t)batch * (N_ * F_);

    unsigned long long acc[8][4];
    #pragma unroll
    for (int i = 0; i < 8; i++)
        #pragma unroll
        for (int p = 0; p < 4; p++) acc[i][p] = 0ull;

    float4 pa[8];  // prefetched A tile fragments
    float4 pb[4];  // prefetched Y tile fragments

    const int NT = N_ / 32;  // 256 k-tiles

    // --- load tile 0 into registers
    {
        #pragma unroll
        for (int j = 0; j < 8; j++) {
            int v = tid + (j << 7);
            int m = v >> 3, kc = (v & 7) << 2;
            pa[j] = *reinterpret_cast<const float4*>(A + (size_t)(m0 + m) * N_ + kc);
        }
        #pragma unroll
        for (int j = 0; j < 4; j++) {
            int v = tid + (j << 7);
            int kr = v >> 4, gc = (v & 15) << 2;
            pb[j] = *reinterpret_cast<const float4*>(Yb + (size_t)kr * 64 + gc);
        }
    }

    for (int t = 0; t < NT; ++t) {
        // ---- stage prefetched tile into smem
        #pragma unroll
        for (int j = 0; j < 8; j++) {
            int v = tid + (j << 7);
            int m = v >> 3, kc = (v & 7) << 2;
            int pg = (m >> 2) ^ (v & 7);        // XOR swizzle, (k>>2)&7 == v&7 here
            int base = (pg << 2) + (m & 3);
            float vals[4] = {pa[j].x, pa[j].y, pa[j].z, pa[j].w};
            #pragma unroll
            for (int i = 0; i < 4; i++) As[(kc + i) * 128 + base] = vals[i];
        }
        #pragma unroll
        for (int j = 0; j < 4; j++) {
            int v = tid + (j << 7);
            int kr = v >> 4, gc = (v & 15) << 2;
            *reinterpret_cast<float4*>(&Bs[kr * 64 + gc]) = pb[j];
        }
        __syncthreads();

        // ---- prefetch next tile (LDGs overlap the compute below)
        if (t + 1 < NT) {
            const int k0 = (t + 1) << 5;
            #pragma unroll
            for (int j = 0; j < 8; j++) {
                int v = tid + (j << 7);
                int m = v >> 3, kc = (v & 7) << 2;
                pa[j] = *reinterpret_cast<const float4*>(A + (size_t)(m0 + m) * N_ + k0 + kc);
            }
            #pragma unroll
            for (int j = 0; j < 4; j++) {
                int v = tid + (j << 7);
                int kr = v >> 4, gc = (v & 15) << 2;
                pb[j] = *reinterpret_cast<const float4*>(Yb + (size_t)(k0 + kr) * 64 + gc);
            }
        }

        // ---- compute 32 k-steps from smem
        #pragma unroll
        for (int k = 0; k < 32; k++) {
            const int sw = (k >> 2) & 7;  // compile-time in unrolled body
            const float4 a0 = *reinterpret_cast<const float4*>(
                &As[(k << 7) + ((((ty << 1)    ) ^ sw) << 2)]);
            const float4 a1 = *reinterpret_cast<const float4*>(
                &As[(k << 7) + ((((ty << 1) | 1) ^ sw) << 2)]);
            const float4 b0 = *reinterpret_cast<const float4*>(&Bs[(k << 6) + (tx << 3)]);
            const float4 b1 = *reinterpret_cast<const float4*>(&Bs[(k << 6) + (tx << 3) + 4]);
            unsigned long long bp[4] = {pk2(b0.x, b0.y), pk2(b0.z, b0.w),
                                        pk2(b1.x, b1.y), pk2(b1.z, b1.w)};
            float av[8] = {a0.x, a0.y, a0.z, a0.w, a1.x, a1.y, a1.z, a1.w};
            #pragma unroll
            for (int i = 0; i < 8; i++) {
                unsigned long long ap = pk2(av[i], av[i]);
                acc[i][0] = fma2(ap, bp[0], acc[i][0]);
                acc[i][1] = fma2(ap, bp[1], acc[i][1]);
                acc[i][2] = fma2(ap, bp[2], acc[i][2]);
                acc[i][3] = fma2(ap, bp[3], acc[i][3]);
            }
        }
        __syncthreads();
    }

    // ---- epilogue: relu + store
    #pragma unroll
    for (int i = 0; i < 8; i++) {
        float o[8];
        #pragma unroll
        for (int p = 0; p < 4; p++) {
            float2 v = upk2(acc[i][p]);
            o[2 * p]     = fmaxf(v.x, 0.f);
            o[2 * p + 1] = fmaxf(v.y, 0.f);
        }
        float4* dst = reinterpret_cast<float4*>(
            Ob + (size_t)(m0 + (ty << 3) + i) * 64 + (tx << 3));
        dst[0] = make_float4(o[0], o[1], o[2], o[3]);
        dst[1] = make_float4(o[4], o[5], o[6], o[7]);
    }
}

// ---------------- launch ----------------
// inputs (metadata order): 0=x [B,N,F] f32, 1=t int (ignored), 2=net_params [L*F*F] f32, 3=A [N,N] f32
extern "C" void kernel_launch(void* const* d_in, const int* in_sizes, int n_in,
                              void* d_out, int out_size) {
    const float* x   = (const float*)d_in[0];
    const float* net = (const float*)d_in[2];
    const float* A   = (const float*)d_in[3];
    float* out = (float*)d_out;

    float *py, *pz;
    cudaGetSymbolAddress((void**)&py, g_y);
    cudaGetSymbolAddress((void**)&pz, g_z);

    dim3 gg(4, 64);  // batch fastest -> 4 CTAs sharing an A row-panel run together (L2 reuse)

    // layer 0:  z1 = relu(A @ (x @ W0))
    zw_kernel<<<(B_ * N_) / 64, 256>>>(x, net, py);
    gemm_relu_kernel<<<gg, 128>>>(A, py, pz);
    // layer 1:  out = relu(A @ (z1 @ W1))
    zw_kernel<<<(B_ * N_) / 64, 256>>>(pz, net + F_ * F_, py);
    gemm_relu_kernel<<<gg, 128>>>(A, py, out);
}

// round 6
// speedup vs baseline: 2.6942x; 2.6942x over previous
#include <cuda_runtime.h>
#include <cstdint>

#define B_ 4
#define N_ 8192
#define F_ 64

// ---- scratch (__device__ globals; allocation-free rule) ----
__device__ float g_yt[256 * N_];     // (Z@W)^T, [n=b*64+f][k], 8 MB
__device__ float g_z[B_ * N_ * F_];  // layer-1 activations, 8 MB

// =================== helpers ===================
__device__ __forceinline__ uint32_t tf32r(float x) {  // round-to-nearest tf32 (sm_80+)
    uint32_t u;
    asm("cvt.rna.tf32.f32 %0, %1;" : "=r"(u) : "f"(x));
    return u;
}

#define MMA_TF32(d, a, b) \
    asm volatile( \
        "mma.sync.aligned.m16n8k8.row.col.f32.tf32.tf32.f32 " \
        "{%0,%1,%2,%3}, {%4,%5,%6,%7}, {%8,%9}, {%0,%1,%2,%3};" \
        : "+f"((d)[0]), "+f"((d)[1]), "+f"((d)[2]), "+f"((d)[3]) \
        : "r"((a)[0]), "r"((a)[1]), "r"((a)[2]), "r"((a)[3]), \
          "r"((b)[0]), "r"((b)[1]))

// =================== small GEMM: Yt = (Z @ W)^T ===================
// Z: [B*N, 64] row-major. Output Yt[n = b*64+f][k], row-major [256][8192].
__global__ __launch_bounds__(256) void zw_t_kernel(const float* __restrict__ Z,
                                                   const float* __restrict__ Wp,
                                                   float* __restrict__ Yt) {
    __shared__ float Ws[64 * 65];
    __shared__ float Zs[64 * 68];
    const int tid = threadIdx.x;
    const int r0 = blockIdx.x * 64;
    const int batch = r0 >> 13;
    const int k0 = r0 & (N_ - 1);

    #pragma unroll
    for (int i = tid; i < 4096; i += 256) Ws[(i >> 6) * 65 + (i & 63)] = Wp[i];
    const float4* Zv = reinterpret_cast<const float4*>(Z + (size_t)r0 * 64);
    #pragma unroll
    for (int i = tid; i < 1024; i += 256) {
        float4 v = Zv[i];
        int r = i >> 4, c = (i & 15) << 2;
        float* p = &Zs[r * 68 + c];
        p[0] = v.x; p[1] = v.y; p[2] = v.z; p[3] = v.w;
    }
    __syncthreads();

    const int r = tid >> 2;
    const int g0 = (tid & 3) << 4;
    float acc[16];
    #pragma unroll
    for (int j = 0; j < 16; j++) acc[j] = 0.f;
    #pragma unroll 8
    for (int f = 0; f < 64; f++) {
        float zv = Zs[r * 68 + f];
        #pragma unroll
        for (int j = 0; j < 16; j++) acc[j] = fmaf(zv, Ws[f * 65 + g0 + j], acc[j]);
    }
    __syncthreads();  // done reading Zs; reuse as transpose staging
    #pragma unroll
    for (int j = 0; j < 16; j++) Zs[(g0 + j) * 68 + r] = acc[j];
    __syncthreads();

    const int f = tid >> 2, kc = (tid & 3) << 4;
    float4* dst = reinterpret_cast<float4*>(Yt + (size_t)(batch * 64 + f) * N_ + k0 + kc);
    const float4* s4 = reinterpret_cast<const float4*>(&Zs[f * 68 + kc]);
    dst[0] = s4[0]; dst[1] = s4[1]; dst[2] = s4[2]; dst[3] = s4[3];
}

// =================== big GEMM: out = relu(A @ Yt^T), tf32 mma.sync ===================
// A: [8192, 8192]; Yt: [256][8192]; out: [B][N][F] with n = b*64+f.
// BM=128, BN=128, BK=32. Grid (2, 64). 256 thr = 8 warps = 4(M) x 2(N), warp tile 32x64.
// Smem holds tiles in FRAGMENT-MAJOR order (m16n8k8 tf32 mapping):
//   A frag reg r for lane T: r0=(row=T/4,   k=T%4), r1=(row+8, k), r2=(row, k+4), r3=(row+8, k+4)
//   B frag reg b for lane T: b0=(k=T%4, n=T/4), b1=(k+4, n)
// so consumers do LDS.128 (A) / LDS.64 (B), conflict-free.
//
// Layout (floats):  [A buf0 | A buf1 | B buf0 | B buf1], each 4*1028 = 4112 floats
//   A addr: s*1028 + mt*128 + T*4 + r      (s=k8 step 0..3, mt=m16 tile 0..7)
//   B addr: s*1028 + nt*64  + T*2 + b      (nt=n8 tile 0..15)
#define SM_BUF 4112
#define NTILES 256
#define SMEM_MMA_BYTES (4 * SM_BUF * 4)

__global__ __launch_bounds__(256) void gcn_mma_kernel(const float* __restrict__ A,
                                                      const float* __restrict__ Yt,
                                                      float* __restrict__ out) {
    extern __shared__ float sm[];
    const int tid = threadIdx.x;
    const int wid = tid >> 5, lane = tid & 31;
    const int wm = wid & 3, wn = wid >> 2;
    const int n0 = blockIdx.x << 7;
    const int m0 = blockIdx.y << 7;

    float acc[2][8][4];
    #pragma unroll
    for (int i = 0; i < 2; i++)
        #pragma unroll
        for (int j = 0; j < 8; j++)
            #pragma unroll
            for (int c = 0; c < 4; c++) acc[i][j][c] = 0.f;

    float4 pa[4], pb[4];
    auto LOADT = [&](int t) {
        const int kk = t << 5;
        #pragma unroll
        for (int j = 0; j < 4; j++) {
            int idx = tid + (j << 8);           // 0..1023
            int row = idx >> 3, k = (idx & 7) << 2;
            pa[j] = *reinterpret_cast<const float4*>(A + (size_t)(m0 + row) * N_ + kk + k);
            pb[j] = *reinterpret_cast<const float4*>(Yt + (size_t)(n0 + row) * N_ + kk + k);
        }
    };
    LOADT(0);

    for (int t = 0; t < NTILES; t++) {
        float* SA = sm + (t & 1) * SM_BUF;
        float* SB = sm + 2 * SM_BUF + (t & 1) * SM_BUF;

        // ---- stage prefetched tile into fragment-major smem (tf32-rounded)
        #pragma unroll
        for (int j = 0; j < 4; j++) {
            int idx = tid + (j << 8);
            int row = idx >> 3, k = (idx & 7) << 2;
            int s = k >> 3;
            // A: reg index from (row, k-half)
            int mt = row >> 4;
            int areg = ((row >> 3) & 1) + (((k >> 2) & 1) << 1);
            int abase = s * 1028 + mt * 128 + ((row & 7) << 4) + areg;  // T*4 = (row&7)*4*4
            float av[4] = {pa[j].x, pa[j].y, pa[j].z, pa[j].w};
            #pragma unroll
            for (int i = 0; i < 4; i++)
                SA[abase + (i << 2)] = __uint_as_float(tf32r(av[i]));
            // B: b index from k-half
            int nt = row >> 3;
            int bb = (k >> 2) & 1;
            int bbase = s * 1028 + nt * 64 + ((row & 7) << 3) + bb;     // T*2 = (row&7)*4*2
            float bv[4] = {pb[j].x, pb[j].y, pb[j].z, pb[j].w};
            #pragma unroll
            for (int i = 0; i < 4; i++)
                SB[bbase + (i << 1)] = __uint_as_float(tf32r(bv[i]));
        }
        __syncthreads();

        if (t + 1 < NTILES) LOADT(t + 1);   // overlap LDG with compute

        // ---- compute: 4 k8-steps
        #pragma unroll
        for (int s = 0; s < 4; s++) {
            uint32_t af[2][4];
            #pragma unroll
            for (int i = 0; i < 2; i++) {
                float4 v = *reinterpret_cast<const float4*>(
                    &SA[s * 1028 + (wm * 2 + i) * 128 + (lane << 2)]);
                af[i][0] = __float_as_uint(v.x); af[i][1] = __float_as_uint(v.y);
                af[i][2] = __float_as_uint(v.z); af[i][3] = __float_as_uint(v.w);
            }
            uint32_t bf[8][2];
            #pragma unroll
            for (int j = 0; j < 8; j++) {
                float2 w = *reinterpret_cast<const float2*>(
                    &SB[s * 1028 + (wn * 8 + j) * 64 + (lane << 1)]);
                bf[j][0] = __float_as_uint(w.x); bf[j][1] = __float_as_uint(w.y);
            }
            #pragma unroll
            for (int i = 0; i < 2; i++)
                #pragma unroll
                for (int j = 0; j < 8; j++) MMA_TF32(acc[i][j], af[i], bf[j]);
        }
        __syncthreads();
    }

    // ---- epilogue: relu + direct store (no split-K, no partials)
    #pragma unroll
    for (int i = 0; i < 2; i++) {
        int mrow = m0 + wm * 32 + i * 16 + (lane >> 2);
        #pragma unroll
        for (int j = 0; j < 8; j++) {
            int n = n0 + wn * 64 + j * 8 + ((lane & 3) << 1);
            int bt = n >> 6, f = n & 63;
            float* d0 = out + ((size_t)bt << 19) + (size_t)mrow * 64 + f;
            *reinterpret_cast<float2*>(d0) =
                make_float2(fmaxf(acc[i][j][0], 0.f), fmaxf(acc[i][j][1], 0.f));
            *reinterpret_cast<float2*>(d0 + 8 * 64) =
                make_float2(fmaxf(acc[i][j][2], 0.f), fmaxf(acc[i][j][3], 0.f));
        }
    }
}

// =================== launch ===================
// inputs: 0=x [B,N,F] f32, 1=t (ignored), 2=net_params [2*64*64] f32, 3=A [N,N] f32
extern "C" void kernel_launch(void* const* d_in, const int* in_sizes, int n_in,
                              void* d_out, int out_size) {
    const float* x   = (const float*)d_in[0];
    const float* net = (const float*)d_in[2];
    const float* A   = (const float*)d_in[3];
    float* out = (float*)d_out;

    float *yt, *z;
    cudaGetSymbolAddress((void**)&yt, g_yt);
    cudaGetSymbolAddress((void**)&z, g_z);

    cudaFuncSetAttribute(gcn_mma_kernel, cudaFuncAttributeMaxDynamicSharedMemorySize,
                         SMEM_MMA_BYTES);

    dim3 gmm(2, 64);
    // layer 0: z = relu(A @ (x @ W0))
    zw_t_kernel<<<512, 256>>>(x, net, yt);
    gcn_mma_kernel<<<gmm, 256, SMEM_MMA_BYTES>>>(A, yt, z);
    // layer 1: out = relu(A @ (z @ W1))
    zw_t_kernel<<<512, 256>>>(z, net + F_ * F_, yt);
    gcn_mma_kernel<<<gmm, 256, SMEM_MMA_BYTES>>>(A, yt, out);
}

// round 7
// speedup vs baseline: 3.5302x; 1.3103x over previous
#include <cuda_runtime.h>
#include <cstdint>

#define B_ 4
#define N_ 8192
#define F_ 64

// ---- scratch (__device__ globals; allocation-free rule) ----
__device__ float g_yt[256 * N_];      // (Z@W)^T tf32-rounded, [n=b*64+f][k], 8 MB
__device__ float g_z[B_ * N_ * F_];   // layer-1 activations, 8 MB
__device__ float g_part[2 * N_ * 256];// split-K partials, 16 MB

// =================== helpers ===================
__device__ __forceinline__ uint32_t s2u(const void* p) {
    uint32_t a;
    asm("{ .reg .u64 t; cvta.to.shared.u64 t, %1; cvt.u32.u64 %0, t; }" : "=r"(a) : "l"(p));
    return a;
}
__device__ __forceinline__ uint32_t tf32r(float x) {  // round-to-nearest tf32 (sm_80+)
    uint32_t u;
    asm("cvt.rna.tf32.f32 %0, %1;" : "=r"(u) : "f"(x));
    return u;
}

#define MMA_TF32(d, a, b) \
    asm volatile( \
        "mma.sync.aligned.m16n8k8.row.col.f32.tf32.tf32.f32 " \
        "{%0,%1,%2,%3}, {%4,%5,%6,%7}, {%8,%9}, {%0,%1,%2,%3};" \
        : "+f"((d)[0]), "+f"((d)[1]), "+f"((d)[2]), "+f"((d)[3]) \
        : "r"((a)[0]), "r"((a)[1]), "r"((a)[2]), "r"((a)[3]), \
          "r"((b)[0]), "r"((b)[1]))

#define LDMX4(d, addr) \
    asm volatile("ldmatrix.sync.aligned.m8n8.x4.shared.b16 {%0,%1,%2,%3}, [%4];" \
        : "=r"((d)[0]), "=r"((d)[1]), "=r"((d)[2]), "=r"((d)[3]) : "r"(addr))

#define STS128U(r0, r1, r2, r3, addr) \
    asm volatile("st.shared.v4.b32 [%0], {%1, %2, %3, %4};" \
        :: "r"(addr), "r"(r0), "r"(r1), "r"(r2), "r"(r3) : "memory")

#define CPASYNC16(dst, src) \
    asm volatile("cp.async.cg.shared.global [%0], [%1], 16;" :: "r"(dst), "l"(src) : "memory")
#define CPASYNC_COMMIT() asm volatile("cp.async.commit_group;" ::: "memory")
#define CPASYNC_WAIT0()  asm volatile("cp.async.wait_group 0;" ::: "memory")

// =================== small GEMM: Yt = tf32_round((Z @ W)^T) ===================
__global__ __launch_bounds__(256) void zw_t_kernel(const float* __restrict__ Z,
                                                   const float* __restrict__ Wp,
                                                   float* __restrict__ Yt) {
    __shared__ float Ws[64 * 65];
    __shared__ float Zs[64 * 68];
    const int tid = threadIdx.x;
    const int r0 = blockIdx.x * 64;
    const int batch = r0 >> 13;
    const int k0 = r0 & (N_ - 1);

    #pragma unroll
    for (int i = tid; i < 4096; i += 256) Ws[(i >> 6) * 65 + (i & 63)] = Wp[i];
    const float4* Zv = reinterpret_cast<const float4*>(Z + (size_t)r0 * 64);
    #pragma unroll
    for (int i = tid; i < 1024; i += 256) {
        float4 v = Zv[i];
        int r = i >> 4, c = (i & 15) << 2;
        float* p = &Zs[r * 68 + c];
        p[0] = v.x; p[1] = v.y; p[2] = v.z; p[3] = v.w;
    }
    __syncthreads();

    const int r = tid >> 2;
    const int g0 = (tid & 3) << 4;
    float acc[16];
    #pragma unroll
    for (int j = 0; j < 16; j++) acc[j] = 0.f;
    #pragma unroll 8
    for (int f = 0; f < 64; f++) {
        float zv = Zs[r * 68 + f];
        #pragma unroll
        for (int j = 0; j < 16; j++) acc[j] = fmaf(zv, Ws[f * 65 + g0 + j], acc[j]);
    }
    __syncthreads();
    // transpose staging, rounding to tf32 so downstream cp.async needs no convert
    #pragma unroll
    for (int j = 0; j < 16; j++)
        Zs[(g0 + j) * 68 + r] = __uint_as_float(tf32r(acc[j]));
    __syncthreads();

    const int f = tid >> 2, kc = (tid & 3) << 4;
    float4* dst = reinterpret_cast<float4*>(Yt + (size_t)(batch * 64 + f) * N_ + k0 + kc);
    const float4* s4 = reinterpret_cast<const float4*>(&Zs[f * 68 + kc]);
    dst[0] = s4[0]; dst[1] = s4[1]; dst[2] = s4[2]; dst[3] = s4[3];
}

// =================== big GEMM: part[sk] = A[:, ks] @ Yt[:, ks]^T ===================
// CTA 128M x 128N x (K/2), 128 threads, 4 warps 2x2, warp tile 64x64, split-K=2.
// Canonical smem tiles [row][32 k-floats], 16B-chunk XOR swizzle; ldmatrix.x4 consumers.
#define NT 128                 // k-tiles per CTA (4096 / 32)
#define SMEM_BYTES 65536       // A: 2 x 16 KB, B: 2 x 16 KB

__global__ __launch_bounds__(128, 2) void gcn_mma_kernel(const float* __restrict__ A,
                                                         const float* __restrict__ Yt,
                                                         float* __restrict__ part) {
    extern __shared__ float sm[];
    const uint32_t sbase = s2u(sm);
    const int tid = threadIdx.x, lane = tid & 31, wid = tid >> 5;
    const int wm = wid & 1, wn = wid >> 1;
    const int n0 = blockIdx.x << 7;
    const int m0 = blockIdx.y << 7;
    const int kb = blockIdx.z << 12;

    // ldmatrix per-lane geometry
    const int r = lane & 7;
    const int amod = (((lane >> 3) & 1) << 3) + r;   // row offset within m16 frag
    const int acoff = lane >> 4;                     // k-chunk offset 0/1
    const int bmod = (((lane >> 4) & 1) << 3) + r;
    const int bcoff = (lane >> 3) & 1;
    const uint32_t aRowB = (uint32_t)(wm * 64 + amod) * 128;
    const uint32_t bRowB = (uint32_t)(wn * 64 + bmod) * 128;

    // staging geometry: thread handles rows (tid>>3)+16j, chunk tid&7
    const int srow = tid >> 3;
    const uint32_t swz = (uint32_t)(((tid & 7) ^ (srow & 7)) << 4);
    const uint32_t stOff = (uint32_t)srow * 128 + swz;

    const float* gA0 = A + (size_t)(m0 + srow) * N_ + kb + ((tid & 7) << 2);
    const float* gB0 = Yt + (size_t)(n0 + srow) * N_ + kb + ((tid & 7) << 2);

    float acc[4][8][4];
    #pragma unroll
    for (int i = 0; i < 4; i++)
        #pragma unroll
        for (int j = 0; j < 8; j++)
            #pragma unroll
            for (int c = 0; c < 4; c++) acc[i][j][c] = 0.f;

    float4 ra[8];
    // ---- prime: B tile 0 via cp.async, A tile 0 into regs
    {
        uint32_t sb = sbase + 32768;
        #pragma unroll
        for (int j = 0; j < 8; j++)
            CPASYNC16(sb + stOff + (uint32_t)j * 2048, gB0 + (size_t)j * (16 * N_));
        CPASYNC_COMMIT();
        #pragma unroll
        for (int j = 0; j < 8; j++)
            ra[j] = *reinterpret_cast<const float4*>(gA0 + (size_t)j * (16 * N_));
    }

    for (int t = 0; t < NT; t++) {
        const uint32_t sa = sbase + (uint32_t)(t & 1) * 16384;
        const uint32_t sb = sbase + 32768 + (uint32_t)(t & 1) * 16384;

        // stage A (tf32-rounded) from prefetch regs
        #pragma unroll
        for (int j = 0; j < 8; j++)
            STS128U(tf32r(ra[j].x), tf32r(ra[j].y), tf32r(ra[j].z), tf32r(ra[j].w),
                    sa + stOff + (uint32_t)j * 2048);
        CPASYNC_WAIT0();      // B(t) landed
        __syncthreads();      // A(t), B(t) visible to all

        if (t + 1 < NT) {     // launch next tile's loads; overlap with compute below
            const uint32_t sbn = sbase + 32768 + (uint32_t)((t + 1) & 1) * 16384;
            const float* gB = gB0 + (size_t)(t + 1) * 32;
            #pragma unroll
            for (int j = 0; j < 8; j++)
                CPASYNC16(sbn + stOff + (uint32_t)j * 2048, gB + (size_t)j * (16 * N_));
            CPASYNC_COMMIT();
            const float* gA = gA0 + (size_t)(t + 1) * 32;
            #pragma unroll
            for (int j = 0; j < 8; j++)
                ra[j] = *reinterpret_cast<const float4*>(gA + (size_t)j * (16 * N_));
        }

        // ---- compute 4 k8-steps
        #pragma unroll
        for (int s = 0; s < 4; s++) {
            uint32_t af[4][4];
            #pragma unroll
            for (int f = 0; f < 4; f++)
                LDMX4(af[f], sa + aRowB + (uint32_t)f * 2048 +
                             (uint32_t)(((2 * s + acoff) ^ r) << 4));
            uint32_t bq[4][4];
            #pragma unroll
            for (int p = 0; p < 4; p++)
                LDMX4(bq[p], sb + bRowB + (uint32_t)p * 2048 +
                             (uint32_t)(((2 * s + bcoff) ^ r) << 4));
            #pragma unroll
            for (int i = 0; i < 4; i++)
                #pragma unroll
                for (int j = 0; j < 8; j++)
                    MMA_TF32(acc[i][j], af[i], &bq[j >> 1][(j & 1) * 2]);
        }
    }

    // ---- epilogue: store split-K partials (no relu yet)
    float* dstb = part + ((size_t)blockIdx.z << 21);
    #pragma unroll
    for (int i = 0; i < 4; i++) {
        int mrow = m0 + wm * 64 + i * 16 + (lane >> 2);
        #pragma unroll
        for (int j = 0; j < 8; j++) {
            int ncol = n0 + wn * 64 + j * 8 + ((lane & 3) << 1);
            float* d0 = dstb + (size_t)mrow * 256 + ncol;
            *reinterpret_cast<float2*>(d0) = make_float2(acc[i][j][0], acc[i][j][1]);
            *reinterpret_cast<float2*>(d0 + 8 * 256) = make_float2(acc[i][j][2], acc[i][j][3]);
        }
    }
}

// =================== reduce 2 split-K partials + relu, scatter to [B,N,F] ===================
__global__ __launch_bounds__(256) void reduce_relu_kernel(const float* __restrict__ part,
                                                          float* __restrict__ out) {
    const int idx = blockIdx.x * 256 + threadIdx.x;  // float4 index over [8192][256]
    const float4* p = reinterpret_cast<const float4*>(part);
    float4 a = p[idx], b = p[idx + 524288];
    float4 rr;
    rr.x = fmaxf(a.x + b.x, 0.f);
    rr.y = fmaxf(a.y + b.y, 0.f);
    rr.z = fmaxf(a.z + b.z, 0.f);
    rr.w = fmaxf(a.w + b.w, 0.f);
    const int m = idx >> 6;
    const int n = (idx & 63) << 2;
    const int bt = n >> 6, f = n & 63;
    *reinterpret_cast<float4*>(out + ((size_t)bt << 19) + (size_t)m * 64 + f) = rr;
}

// =================== launch ===================
// inputs: 0=x [B,N,F] f32, 1=t (ignored), 2=net_params [2*64*64] f32, 3=A [N,N] f32
extern "C" void kernel_launch(void* const* d_in, const int* in_sizes, int n_in,
                              void* d_out, int out_size) {
    const float* x   = (const float*)d_in[0];
    const float* net = (const float*)d_in[2];
    const float* A   = (const float*)d_in[3];
    float* out = (float*)d_out;

    float *yt, *z, *part;
    cudaGetSymbolAddress((void**)&yt, g_yt);
    cudaGetSymbolAddress((void**)&z, g_z);
    cudaGetSymbolAddress((void**)&part, g_part);

    cudaFuncSetAttribute(gcn_mma_kernel, cudaFuncAttributeMaxDynamicSharedMemorySize,
                         SMEM_BYTES);

    dim3 gmm(2, 64, 2);
    // layer 0: z = relu(A @ (x @ W0))
    zw_t_kernel<<<512, 256>>>(x, net, yt);
    gcn_mma_kernel<<<gmm, 128, SMEM_BYTES>>>(A, yt, part);
    reduce_relu_kernel<<<2048, 256>>>(part, z);
    // layer 1: out = relu(A @ (z @ W1))
    zw_t_kernel<<<512, 256>>>(z, net + F_ * F_, yt);
    gcn_mma_kernel<<<gmm, 128, SMEM_BYTES>>>(A, yt, part);
    reduce_relu_kernel<<<2048, 256>>>(part, out);
}

// round 10
// speedup vs baseline: 3.8132x; 1.0802x over previous
#include <cuda_runtime.h>
#include <cstdint>

#define B_ 4
#define N_ 8192
#define F_ 64

// ---- scratch (__device__ globals; allocation-free rule) ----
__device__ float g_yt[256 * N_];      // (Z@W)^T tf32-rounded, [n=b*64+f][k], 8 MB
__device__ float g_z[B_ * N_ * F_];   // layer-1 activations, 8 MB
__device__ float g_part[2 * N_ * 256];// split-K partials, 16 MB

// =================== helpers ===================
__device__ __forceinline__ uint32_t s2u(const void* p) {
    uint32_t a;
    asm("{ .reg .u64 t; cvta.to.shared.u64 t, %1; cvt.u32.u64 %0, t; }" : "=r"(a) : "l"(p));
    return a;
}
__device__ __forceinline__ uint32_t tf32r(float x) {  // round-to-nearest tf32 (sm_80+)
    uint32_t u;
    asm("cvt.rna.tf32.f32 %0, %1;" : "=r"(u) : "f"(x));
    return u;
}
__device__ __forceinline__ uint32_t tf32ru(uint32_t x) {
    uint32_t u;
    asm("cvt.rna.tf32.f32 %0, %1;" : "=r"(u) : "f"(__uint_as_float(x)));
    return u;
}

#define MMA_TF32(d, a, b) \
    asm volatile( \
        "mma.sync.aligned.m16n8k8.row.col.f32.tf32.tf32.f32 " \
        "{%0,%1,%2,%3}, {%4,%5,%6,%7}, {%8,%9}, {%0,%1,%2,%3};" \
        : "+f"((d)[0]), "+f"((d)[1]), "+f"((d)[2]), "+f"((d)[3]) \
        : "r"((a)[0]), "r"((a)[1]), "r"((a)[2]), "r"((a)[3]), \
          "r"((b)[0]), "r"((b)[1]))

#define LDMX4(d, addr) \
    asm volatile("ldmatrix.sync.aligned.m8n8.x4.shared.b16 {%0,%1,%2,%3}, [%4];" \
        : "=r"((d)[0]), "=r"((d)[1]), "=r"((d)[2]), "=r"((d)[3]) : "r"(addr))

#define CPASYNC16(dst, src) \
    asm volatile("cp.async.cg.shared.global [%0], [%1], 16;" :: "r"(dst), "l"(src) : "memory")
#define CPASYNC_COMMIT() asm volatile("cp.async.commit_group;" ::: "memory")
#define CPASYNC_WAIT0()  asm volatile("cp.async.wait_group 0;" ::: "memory")
#define CPASYNC_WAIT1()  asm volatile("cp.async.wait_group 1;" ::: "memory")

// =================== small GEMM: Yt = tf32_round((Z @ W)^T) ===================
// Vectorized: W rows 16B-aligned (stride 68), inner loop = 1 scalar LDS + 4 LDS.128.
__global__ __launch_bounds__(256) void zw_t_kernel(const float* __restrict__ Z,
                                                   const float* __restrict__ Wp,
                                                   float* __restrict__ Yt) {
    __shared__ float Ws[64 * 68];
    __shared__ float Zs[64 * 68];
    const int tid = threadIdx.x;
    const int r0 = blockIdx.x * 64;
    const int batch = r0 >> 13;
    const int k0 = r0 & (N_ - 1);

    #pragma unroll
    for (int i = tid; i < 4096; i += 256) Ws[(i >> 6) * 68 + (i & 63)] = Wp[i];
    const float4* Zv = reinterpret_cast<const float4*>(Z + (size_t)r0 * 64);
    #pragma unroll
    for (int i = tid; i < 1024; i += 256) {
        float4 v = Zv[i];
        int r = i >> 4, c = (i & 15) << 2;
        float* p = &Zs[r * 68 + c];
        p[0] = v.x; p[1] = v.y; p[2] = v.z; p[3] = v.w;
    }
    __syncthreads();

    const int r = tid >> 2;
    const int g0 = (tid & 3) << 4;
    float4 a0 = make_float4(0.f, 0.f, 0.f, 0.f), a1 = a0, a2 = a0, a3 = a0;
    #pragma unroll 16
    for (int f = 0; f < 64; f++) {
        float zv = Zs[r * 68 + f];
        const float4* wr = reinterpret_cast<const float4*>(&Ws[f * 68 + g0]);
        float4 w0 = wr[0], w1 = wr[1], w2 = wr[2], w3 = wr[3];
        a0.x = fmaf(zv, w0.x, a0.x); a0.y = fmaf(zv, w0.y, a0.y);
        a0.z = fmaf(zv, w0.z, a0.z); a0.w = fmaf(zv, w0.w, a0.w);
        a1.x = fmaf(zv, w1.x, a1.x); a1.y = fmaf(zv, w1.y, a1.y);
        a1.z = fmaf(zv, w1.z, a1.z); a1.w = fmaf(zv, w1.w, a1.w);
        a2.x = fmaf(zv, w2.x, a2.x); a2.y = fmaf(zv, w2.y, a2.y);
        a2.z = fmaf(zv, w2.z, a2.z); a2.w = fmaf(zv, w2.w, a2.w);
        a3.x = fmaf(zv, w3.x, a3.x); a3.y = fmaf(zv, w3.y, a3.y);
        a3.z = fmaf(zv, w3.z, a3.z); a3.w = fmaf(zv, w3.w, a3.w);
    }
    __syncthreads();
    // transpose staging, rounding to tf32 so downstream cp.async needs no convert
    float av[16] = {a0.x, a0.y, a0.z, a0.w, a1.x, a1.y, a1.z, a1.w,
                    a2.x, a2.y, a2.z, a2.w, a3.x, a3.y, a3.z, a3.w};
    #pragma unroll
    for (int j = 0; j < 16; j++)
        Zs[(g0 + j) * 68 + r] = __uint_as_float(tf32r(av[j]));
    __syncthreads();

    const int f = tid >> 2, kc = (tid & 3) << 4;
    float4* dst = reinterpret_cast<float4*>(Yt + (size_t)(batch * 64 + f) * N_ + k0 + kc);
    const float4* s4 = reinterpret_cast<const float4*>(&Zs[f * 68 + kc]);
    dst[0] = s4[0]; dst[1] = s4[1]; dst[2] = s4[2]; dst[3] = s4[3];
}

// =================== big GEMM: part[sk] = A[:, ks] @ Yt[:, ks]^T ===================
// CTA 128M x 128N x (K/2), 128 threads, 4 warps 2x2, warp tile 64x64, split-K=2.
// 3-stage cp.async pipeline for BOTH operands; A rounded to tf32 post-ldmatrix.
#define NT 128                 // k-tiles per CTA (4096 / 32)
#define STAGE_B 16384          // bytes per operand tile
#define SMEM_BYTES (6 * STAGE_B)

__global__ __launch_bounds__(128, 2) void gcn_mma_kernel(const float* __restrict__ A,
                                                         const float* __restrict__ Yt,
                                                         float* __restrict__ part) {
    extern __shared__ float sm[];
    const uint32_t sbase = s2u(sm);
    const int tid = threadIdx.x, lane = tid & 31, wid = tid >> 5;
    const int wm = wid & 1, wn = wid >> 1;
    const int n0 = blockIdx.x << 7;
    const int m0 = blockIdx.y << 7;
    const int kb = blockIdx.z << 12;

    // ldmatrix per-lane geometry
    const int r = lane & 7;
    const int amod = (((lane >> 3) & 1) << 3) + r;
    const int acoff = lane >> 4;
    const int bmod = (((lane >> 4) & 1) << 3) + r;
    const int bcoff = (lane >> 3) & 1;
    const uint32_t aRowB = (uint32_t)(wm * 64 + amod) * 128;
    const uint32_t bRowB = (uint32_t)(wn * 64 + bmod) * 128;

    // staging geometry: thread covers rows (tid>>3)+16j, 16B chunk tid&7
    const int srow = tid >> 3;
    const uint32_t stOff = (uint32_t)srow * 128 + (uint32_t)(((tid & 7) ^ (srow & 7)) << 4);

    const float* gA0 = A + (size_t)(m0 + srow) * N_ + kb + ((tid & 7) << 2);
    const float* gB0 = Yt + (size_t)(n0 + srow) * N_ + kb + ((tid & 7) << 2);

    float acc[4][8][4];
    #pragma unroll
    for (int i = 0; i < 4; i++)
        #pragma unroll
        for (int j = 0; j < 8; j++)
            #pragma unroll
            for (int c = 0; c < 4; c++) acc[i][j][c] = 0.f;

    auto ISSUE = [&](int t) {
        const uint32_t stg = (uint32_t)(t % 3) * STAGE_B;
        const float* gA = gA0 + (size_t)t * 32;
        const float* gB = gB0 + (size_t)t * 32;
        #pragma unroll
        for (int j = 0; j < 8; j++)
            CPASYNC16(sbase + stg + stOff + (uint32_t)j * 2048, gA + (size_t)j * (16 * N_));
        #pragma unroll
        for (int j = 0; j < 8; j++)
            CPASYNC16(sbase + 3 * STAGE_B + stg + stOff + (uint32_t)j * 2048,
                      gB + (size_t)j * (16 * N_));
        CPASYNC_COMMIT();
    };
    ISSUE(0);
    ISSUE(1);

    for (int t = 0; t < NT; t++) {
        const uint32_t stg = (uint32_t)(t % 3) * STAGE_B;
        const uint32_t sa = sbase + stg;
        const uint32_t sb = sbase + 3 * STAGE_B + stg;

        if (t + 1 < NT) { CPASYNC_WAIT1(); } else { CPASYNC_WAIT0(); }
        __syncthreads();

        if (t + 2 < NT) ISSUE(t + 2);   // overlap next-next tile with compute

        // ---- compute 4 k8-steps; A rounded to tf32 in registers
        #pragma unroll
        for (int s = 0; s < 4; s++) {
            uint32_t af[4][4];
            #pragma unroll
            for (int f = 0; f < 4; f++) {
                LDMX4(af[f], sa + aRowB + (uint32_t)f * 2048 +
                             (uint32_t)(((2 * s + acoff) ^ r) << 4));
                af[f][0] = tf32ru(af[f][0]); af[f][1] = tf32ru(af[f][1]);
                af[f][2] = tf32ru(af[f][2]); af[f][3] = tf32ru(af[f][3]);
            }
            uint32_t bq[4][4];
            #pragma unroll
            for (int p = 0; p < 4; p++)
                LDMX4(bq[p], sb + bRowB + (uint32_t)p * 2048 +
                             (uint32_t)(((2 * s + bcoff) ^ r) << 4));
            #pragma unroll
            for (int i = 0; i < 4; i++)
                #pragma unroll
                for (int j = 0; j < 8; j++)
                    MMA_TF32(acc[i][j], af[i], &bq[j >> 1][(j & 1) * 2]);
        }
        __syncthreads();
    }

    // ---- epilogue: store split-K partials
    float* dstb = part + ((size_t)blockIdx.z << 21);
    #pragma unroll
    for (int i = 0; i < 4; i++) {
        int mrow = m0 + wm * 64 + i * 16 + (lane >> 2);
        #pragma unroll
        for (int j = 0; j < 8; j++) {
            int ncol = n0 + wn * 64 + j * 8 + ((lane & 3) << 1);
            float* d0 = dstb + (size_t)mrow * 256 + ncol;
            *reinterpret_cast<float2*>(d0) = make_float2(acc[i][j][0], acc[i][j][1]);
            *reinterpret_cast<float2*>(d0 + 8 * 256) = make_float2(acc[i][j][2], acc[i][j][3]);
        }
    }
}

// =================== reduce 2 split-K partials + relu, scatter to [B,N,F] ===================
__global__ __launch_bounds__(256) void reduce_relu_kernel(const float* __restrict__ part,
                                                          float* __restrict__ out) {
    const int idx = blockIdx.x * 256 + threadIdx.x;  // float4 index over [8192][256]
    const float4* p = reinterpret_cast<const float4*>(part);
    float4 a = p[idx], b = p[idx + 524288];
    float4 rr;
    rr.x = fmaxf(a.x + b.x, 0.f);
    rr.y = fmaxf(a.y + b.y, 0.f);
    rr.z = fmaxf(a.z + b.z, 0.f);
    rr.w = fmaxf(a.w + b.w, 0.f);
    const int m = idx >> 6;
    const int n = (idx & 63) << 2;
    const int bt = n >> 6, f = n & 63;
    *reinterpret_cast<float4*>(out + ((size_t)bt << 19) + (size_t)m * 64 + f) = rr;
}

// =================== launch ===================
// inputs: 0=x [B,N,F] f32, 1=t (ignored), 2=net_params [2*64*64] f32, 3=A [N,N] f32
extern "C" void kernel_launch(void* const* d_in, const int* in_sizes, int n_in,
                              void* d_out, int out_size) {
    const float* x   = (const float*)d_in[0];
    const float* net = (const float*)d_in[2];
    const float* A   = (const float*)d_in[3];
    float* out = (float*)d_out;

    float *yt, *z, *part;
    cudaGetSymbolAddress((void**)&yt, g_yt);
    cudaGetSymbolAddress((void**)&z, g_z);
    cudaGetSymbolAddress((void**)&part, g_part);

    cudaFuncSetAttribute(gcn_mma_kernel, cudaFuncAttributeMaxDynamicSharedMemorySize,
                         SMEM_BYTES);

    dim3 gmm(2, 64, 2);
    // layer 0: z = relu(A @ (x @ W0))
    zw_t_kernel<<<512, 256>>>(x, net, yt);
    gcn_mma_kernel<<<gmm, 128, SMEM_BYTES>>>(A, yt, part);
    reduce_relu_kernel<<<2048, 256>>>(part, z);
    // layer 1: out = relu(A @ (z @ W1))
    zw_t_kernel<<<512, 256>>>(z, net + F_ * F_, yt);
    gcn_mma_kernel<<<gmm, 128, SMEM_BYTES>>>(A, yt, part);
    reduce_relu_kernel<<<2048, 256>>>(part, out);
}

// round 11
// speedup vs baseline: 3.9019x; 1.0233x over previous
#include <cuda_runtime.h>
#include <cstdint>

#define B_ 4
#define N_ 8192
#define F_ 64

// ---- scratch (__device__ globals; allocation-free rule) ----
__device__ float g_yt[256 * N_];      // (Z@W)^T tf32-rounded, [n=b*64+f][k], 8 MB
__device__ float g_z[B_ * N_ * F_];   // layer-1 activations, 8 MB
__device__ float g_part[2 * N_ * 256];// split-K partials, 16 MB

// =================== helpers ===================
__device__ __forceinline__ uint32_t s2u(const void* p) {
    uint32_t a;
    asm("{ .reg .u64 t; cvta.to.shared.u64 t, %1; cvt.u32.u64 %0, t; }" : "=r"(a) : "l"(p));
    return a;
}
__device__ __forceinline__ uint32_t tf32r(float x) {  // round-to-nearest tf32 (sm_80+)
    uint32_t u;
    asm("cvt.rna.tf32.f32 %0, %1;" : "=r"(u) : "f"(x));
    return u;
}
__device__ __forceinline__ uint32_t tf32ru(uint32_t x) {
    uint32_t u;
    asm("cvt.rna.tf32.f32 %0, %1;" : "=r"(u) : "f"(__uint_as_float(x)));
    return u;
}

#define MMA_TF32(d, a, b) \
    asm volatile( \
        "mma.sync.aligned.m16n8k8.row.col.f32.tf32.tf32.f32 " \
        "{%0,%1,%2,%3}, {%4,%5,%6,%7}, {%8,%9}, {%0,%1,%2,%3};" \
        : "+f"((d)[0]), "+f"((d)[1]), "+f"((d)[2]), "+f"((d)[3]) \
        : "r"((a)[0]), "r"((a)[1]), "r"((a)[2]), "r"((a)[3]), \
          "r"((b)[0]), "r"((b)[1]))

#define LDMX4(d, addr) \
    asm volatile("ldmatrix.sync.aligned.m8n8.x4.shared.b16 {%0,%1,%2,%3}, [%4];" \
        : "=r"((d)[0]), "=r"((d)[1]), "=r"((d)[2]), "=r"((d)[3]) : "r"(addr))

#define CPASYNC16(dst, src) \
    asm volatile("cp.async.cg.shared.global [%0], [%1], 16;" :: "r"(dst), "l"(src) : "memory")
#define CPASYNC_COMMIT() asm volatile("cp.async.commit_group;" ::: "memory")
#define CPASYNC_WAIT0()  asm volatile("cp.async.wait_group 0;" ::: "memory")
#define CPASYNC_WAIT1()  asm volatile("cp.async.wait_group 1;" ::: "memory")

// =================== small GEMM: Yt = tf32_round((Z @ W)^T) ===================
// Regridded for occupancy: 1024 CTAs x 128 threads, 32 rows per CTA.
// Per-row math identical to previous round (bit-identical output).
__global__ __launch_bounds__(128) void zw_t_kernel(const float* __restrict__ Z,
                                                   const float* __restrict__ Wp,
                                                   float* __restrict__ Yt) {
    __shared__ float Ws[64 * 68];    // weights, 16B-aligned rows
    __shared__ float Zin[32 * 68];   // input rows
    __shared__ float Zout[64 * 33];  // transposed tf32-rounded output staging
    const int tid = threadIdx.x;
    const int r0 = blockIdx.x * 32;
    const int batch = r0 >> 13;
    const int k0 = r0 & (N_ - 1);

    #pragma unroll
    for (int i = tid; i < 4096; i += 128) Ws[(i >> 6) * 68 + (i & 63)] = Wp[i];
    const float4* Zv = reinterpret_cast<const float4*>(Z + (size_t)r0 * 64);
    #pragma unroll
    for (int i = tid; i < 512; i += 128) {
        float4 v = Zv[i];
        int r = i >> 4, c = (i & 15) << 2;
        float* p = &Zin[r * 68 + c];
        p[0] = v.x; p[1] = v.y; p[2] = v.z; p[3] = v.w;
    }
    __syncthreads();

    const int r = tid >> 2;          // 0..31
    const int g0 = (tid & 3) << 4;   // 0,16,32,48
    float4 a0 = make_float4(0.f, 0.f, 0.f, 0.f), a1 = a0, a2 = a0, a3 = a0;
    #pragma unroll 16
    for (int f = 0; f < 64; f++) {
        float zv = Zin[r * 68 + f];
        const float4* wr = reinterpret_cast<const float4*>(&Ws[f * 68 + g0]);
        float4 w0 = wr[0], w1 = wr[1], w2 = wr[2], w3 = wr[3];
        a0.x = fmaf(zv, w0.x, a0.x); a0.y = fmaf(zv, w0.y, a0.y);
        a0.z = fmaf(zv, w0.z, a0.z); a0.w = fmaf(zv, w0.w, a0.w);
        a1.x = fmaf(zv, w1.x, a1.x); a1.y = fmaf(zv, w1.y, a1.y);
        a1.z = fmaf(zv, w1.z, a1.z); a1.w = fmaf(zv, w1.w, a1.w);
        a2.x = fmaf(zv, w2.x, a2.x); a2.y = fmaf(zv, w2.y, a2.y);
        a2.z = fmaf(zv, w2.z, a2.z); a2.w = fmaf(zv, w2.w, a2.w);
        a3.x = fmaf(zv, w3.x, a3.x); a3.y = fmaf(zv, w3.y, a3.y);
        a3.z = fmaf(zv, w3.z, a3.z); a3.w = fmaf(zv, w3.w, a3.w);
    }
    // transpose staging, tf32-rounded (downstream cp.async needs no convert)
    float av[16] = {a0.x, a0.y, a0.z, a0.w, a1.x, a1.y, a1.z, a1.w,
                    a2.x, a2.y, a2.z, a2.w, a3.x, a3.y, a3.z, a3.w};
    #pragma unroll
    for (int j = 0; j < 16; j++)
        Zout[(g0 + j) * 33 + r] = __uint_as_float(tf32r(av[j]));
    __syncthreads();

    // store: thread t -> feature f = t>>1, k-chunk kc = (t&1)*16 (16 floats)
    const int f = tid >> 1, kc = (tid & 1) << 4;
    float* dst = Yt + (size_t)(batch * 64 + f) * N_ + k0 + kc;
    const float* srcp = &Zout[f * 33 + kc];
    #pragma unroll
    for (int j = 0; j < 16; j += 4) {
        *reinterpret_cast<float4*>(dst + j) =
            make_float4(srcp[j], srcp[j + 1], srcp[j + 2], srcp[j + 3]);
    }
}

// =================== big GEMM: part[sk] = A[:, ks] @ Yt[:, ks]^T ===================
// CTA 128M x 128N x (K/2), 128 threads, 4 warps 2x2, warp tile 64x64, split-K=2.
// 3-stage cp.async pipeline for BOTH operands; A rounded to tf32 post-ldmatrix.
#define NT 128                 // k-tiles per CTA (4096 / 32)
#define STAGE_B 16384          // bytes per operand tile
#define SMEM_BYTES (6 * STAGE_B)

__global__ __launch_bounds__(128, 2) void gcn_mma_kernel(const float* __restrict__ A,
                                                         const float* __restrict__ Yt,
                                                         float* __restrict__ part) {
    extern __shared__ float sm[];
    const uint32_t sbase = s2u(sm);
    const int tid = threadIdx.x, lane = tid & 31, wid = tid >> 5;
    const int wm = wid & 1, wn = wid >> 1;
    const int n0 = blockIdx.x << 7;
    const int m0 = blockIdx.y << 7;
    const int kb = blockIdx.z << 12;

    // ldmatrix per-lane geometry
    const int r = lane & 7;
    const int amod = (((lane >> 3) & 1) << 3) + r;
    const int acoff = lane >> 4;
    const int bmod = (((lane >> 4) & 1) << 3) + r;
    const int bcoff = (lane >> 3) & 1;
    const uint32_t aRowB = (uint32_t)(wm * 64 + amod) * 128;
    const uint32_t bRowB = (uint32_t)(wn * 64 + bmod) * 128;

    // staging geometry: thread covers rows (tid>>3)+16j, 16B chunk tid&7
    const int srow = tid >> 3;
    const uint32_t stOff = (uint32_t)srow * 128 + (uint32_t)(((tid & 7) ^ (srow & 7)) << 4);

    const float* gA0 = A + (size_t)(m0 + srow) * N_ + kb + ((tid & 7) << 2);
    const float* gB0 = Yt + (size_t)(n0 + srow) * N_ + kb + ((tid & 7) << 2);

    float acc[4][8][4];
    #pragma unroll
    for (int i = 0; i < 4; i++)
        #pragma unroll
        for (int j = 0; j < 8; j++)
            #pragma unroll
            for (int c = 0; c < 4; c++) acc[i][j][c] = 0.f;

    auto ISSUE = [&](int t) {
        const uint32_t stg = (uint32_t)(t % 3) * STAGE_B;
        const float* gA = gA0 + (size_t)t * 32;
        const float* gB = gB0 + (size_t)t * 32;
        #pragma unroll
        for (int j = 0; j < 8; j++)
            CPASYNC16(sbase + stg + stOff + (uint32_t)j * 2048, gA + (size_t)j * (16 * N_));
        #pragma unroll
        for (int j = 0; j < 8; j++)
            CPASYNC16(sbase + 3 * STAGE_B + stg + stOff + (uint32_t)j * 2048,
                      gB + (size_t)j * (16 * N_));
        CPASYNC_COMMIT();
    };
    ISSUE(0);
    ISSUE(1);

    for (int t = 0; t < NT; t++) {
        const uint32_t stg = (uint32_t)(t % 3) * STAGE_B;
        const uint32_t sa = sbase + stg;
        const uint32_t sb = sbase + 3 * STAGE_B + stg;

        if (t + 1 < NT) { CPASYNC_WAIT1(); } else { CPASYNC_WAIT0(); }
        __syncthreads();

        if (t + 2 < NT) ISSUE(t + 2);   // overlap next-next tile with compute

        // ---- compute 4 k8-steps; A rounded to tf32 in registers
        #pragma unroll
        for (int s = 0; s < 4; s++) {
            uint32_t af[4][4];
            #pragma unroll
            for (int f = 0; f < 4; f++) {
                LDMX4(af[f], sa + aRowB + (uint32_t)f * 2048 +
                             (uint32_t)(((2 * s + acoff) ^ r) << 4));
                af[f][0] = tf32ru(af[f][0]); af[f][1] = tf32ru(af[f][1]);
                af[f][2] = tf32ru(af[f][2]); af[f][3] = tf32ru(af[f][3]);
            }
            uint32_t bq[4][4];
            #pragma unroll
            for (int p = 0; p < 4; p++)
                LDMX4(bq[p], sb + bRowB + (uint32_t)p * 2048 +
                             (uint32_t)(((2 * s + bcoff) ^ r) << 4));
            #pragma unroll
            for (int i = 0; i < 4; i++)
                #pragma unroll
                for (int j = 0; j < 8; j++)
                    MMA_TF32(acc[i][j], af[i], &bq[j >> 1][(j & 1) * 2]);
        }
        __syncthreads();
    }

    // ---- epilogue: store split-K partials
    float* dstb = part + ((size_t)blockIdx.z << 21);
    #pragma unroll
    for (int i = 0; i < 4; i++) {
        int mrow = m0 + wm * 64 + i * 16 + (lane >> 2);
        #pragma unroll
        for (int j = 0; j < 8; j++) {
            int ncol = n0 + wn * 64 + j * 8 + ((lane & 3) << 1);
            float* d0 = dstb + (size_t)mrow * 256 + ncol;
            *reinterpret_cast<float2*>(d0) = make_float2(acc[i][j][0], acc[i][j][1]);
            *reinterpret_cast<float2*>(d0 + 8 * 256) = make_float2(acc[i][j][2], acc[i][j][3]);
        }
    }
}

// =================== reduce 2 split-K partials + relu, scatter to [B,N,F] ===================
__global__ __launch_bounds__(256) void reduce_relu_kernel(const float* __restrict__ part,
                                                          float* __restrict__ out) {
    const int idx = blockIdx.x * 256 + threadIdx.x;  // float4 index over [8192][256]
    const float4* p = reinterpret_cast<const float4*>(part);
    float4 a = p[idx], b = p[idx + 524288];
    float4 rr;
    rr.x = fmaxf(a.x + b.x, 0.f);
    rr.y = fmaxf(a.y + b.y, 0.f);
    rr.z = fmaxf(a.z + b.z, 0.f);
    rr.w = fmaxf(a.w + b.w, 0.f);
    const int m = idx >> 6;
    const int n = (idx & 63) << 2;
    const int bt = n >> 6, f = n & 63;
    *reinterpret_cast<float4*>(out + ((size_t)bt << 19) + (size_t)m * 64 + f) = rr;
}

// =================== launch ===================
// inputs: 0=x [B,N,F] f32, 1=t (ignored), 2=net_params [2*64*64] f32, 3=A [N,N] f32
extern "C" void kernel_launch(void* const* d_in, const int* in_sizes, int n_in,
                              void* d_out, int out_size) {
    const float* x   = (const float*)d_in[0];
    const float* net = (const float*)d_in[2];
    const float* A   = (const float*)d_in[3];
    float* out = (float*)d_out;

    float *yt, *z, *part;
    cudaGetSymbolAddress((void**)&yt, g_yt);
    cudaGetSymbolAddress((void**)&z, g_z);
    cudaGetSymbolAddress((void**)&part, g_part);

    cudaFuncSetAttribute(gcn_mma_kernel, cudaFuncAttributeMaxDynamicSharedMemorySize,
                         SMEM_BYTES);

    dim3 gmm(2, 64, 2);
    // layer 0: z = relu(A @ (x @ W0))
    zw_t_kernel<<<1024, 128>>>(x, net, yt);
    gcn_mma_kernel<<<gmm, 128, SMEM_BYTES>>>(A, yt, part);
    reduce_relu_kernel<<<2048, 256>>>(part, z);
    // layer 1: out = relu(A @ (z @ W1))
    zw_t_kernel<<<1024, 128>>>(z, net + F_ * F_, yt);
    gcn_mma_kernel<<<gmm, 128, SMEM_BYTES>>>(A, yt, part);
    reduce_relu_kernel<<<2048, 256>>>(part, out);
}